// round 1
// baseline (speedup 1.0000x reference)
#include <cuda_runtime.h>
#include <cstdint>

// ---------------------------------------------------------------------------
// P2G quadratic B-spline scatter, 64^3 grid, up to B=8 batches.
// out[b, cell] = sum_p w_p * prob_p / (sum_p w_p + 1e-7)
//
// Strategy:
//  - float2 scratch grid (weight, weight*prob) in __device__ global memory
//    (16 MB -> L2-resident on GB300's 126 MB L2).
//  - one thread per particle, fully unrolled 3x3x3 stencil,
//    vector reduction red.global.add.v2.f32 (27 vec-atomics/particle instead
//    of 54 scalar atomics).
//  - finalize pass does the divide into d_out.
// ---------------------------------------------------------------------------

#define GRID_N   64
#define GRID_N3  (GRID_N * GRID_N * GRID_N)
#define B_MAX    8
#define NCELL    (B_MAX * GRID_N3)

__device__ float2 g_acc[NCELL];   // (weight, weight*prob)

// ---------------------------------------------------------------------------

__global__ void p2g_zero_kernel() {
    int i = blockIdx.x * blockDim.x + threadIdx.x;
    // NCELL float2 = NCELL/2 float4 stores
    float4* p = reinterpret_cast<float4*>(g_acc);
    if (i < NCELL / 2) {
        p[i] = make_float4(0.f, 0.f, 0.f, 0.f);
    }
}

// ---------------------------------------------------------------------------

__device__ __forceinline__ void red_add_v2(float2* addr, float a, float b) {
    asm volatile("red.global.add.v2.f32 [%0], {%1, %2};"
                 :: "l"(addr), "f"(a), "f"(b)
                 : "memory");
}

__global__ void __launch_bounds__(256)
p2g_scatter_kernel(const float* __restrict__ pos,
                   const float* __restrict__ prob,
                   const int*   __restrict__ bidx,
                   int L) {
    int i = blockIdx.x * blockDim.x + threadIdx.x;
    if (i >= L) return;

    const float EPS_CLIP = 1e-5f;
    const float HI       = 1.0f - 1e-5f;   // DX * GRID_NUM - eps

    float px = pos[3 * i + 0];
    float py = pos[3 * i + 1];
    float pz = pos[3 * i + 2];
    px = fminf(fmaxf(px, EPS_CLIP), HI);
    py = fminf(fmaxf(py, EPS_CLIP), HI);
    pz = fminf(fmaxf(pz, EPS_CLIP), HI);

    // Xp = pos / DX = pos * 64
    float Xx = px * 64.0f;
    float Xy = py * 64.0f;
    float Xz = pz * 64.0f;

    int bx = min((int)Xx, GRID_N - 1);
    int by = min((int)Xy, GRID_N - 1);
    int bz = min((int)Xz, GRID_N - 1);

    float fx = Xx - (float)bx;
    float fy = Xy - (float)by;
    float fz = Xz - (float)bz;

    // quadratic B-spline weights for taps -1, 0, +1
    float wx[3], wy[3], wz[3];
    wx[0] = 0.5f * (1.0f - fx) * (1.0f - fx);
    wx[1] = 0.75f - (fx - 0.5f) * (fx - 0.5f);
    wx[2] = 0.5f * fx * fx;
    wy[0] = 0.5f * (1.0f - fy) * (1.0f - fy);
    wy[1] = 0.75f - (fy - 0.5f) * (fy - 0.5f);
    wy[2] = 0.5f * fy * fy;
    wz[0] = 0.5f * (1.0f - fz) * (1.0f - fz);
    wz[1] = 0.75f - (fz - 0.5f) * (fz - 0.5f);
    wz[2] = 0.5f * fz * fz;

    float p_val = prob[i];
    int   bofs  = bidx[i] * GRID_N3;

    #pragma unroll
    for (int ox = 0; ox < 3; ox++) {
        int tx = bx - 1 + ox;
        if ((unsigned)tx >= (unsigned)GRID_N) continue;
        int xoff = bofs + tx * (GRID_N * GRID_N);
        #pragma unroll
        for (int oy = 0; oy < 3; oy++) {
            int ty = by - 1 + oy;
            if ((unsigned)ty >= (unsigned)GRID_N) continue;
            float wxy  = wx[ox] * wy[oy];
            int   yoff = xoff + ty * GRID_N;
            #pragma unroll
            for (int oz = 0; oz < 3; oz++) {
                int tz = bz - 1 + oz;
                if ((unsigned)tz >= (unsigned)GRID_N) continue;
                float w = wxy * wz[oz];
                red_add_v2(&g_acc[yoff + tz], w, w * p_val);
            }
        }
    }
}

// ---------------------------------------------------------------------------

__global__ void p2g_finalize_kernel(float* __restrict__ out, int n) {
    int i = blockIdx.x * blockDim.x + threadIdx.x;
    if (i < n) {
        float2 a = g_acc[i];
        out[i] = a.y / (a.x + 1e-7f);
    }
}

// ---------------------------------------------------------------------------

extern "C" void kernel_launch(void* const* d_in, const int* in_sizes, int n_in,
                              void* d_out, int out_size) {
    const float* pos  = (const float*)d_in[0];
    const float* prob = (const float*)d_in[1];
    const int*   bidx = (const int*)d_in[2];
    float*       out  = (float*)d_out;

    int L = in_sizes[1];            // element count of prob == particle count

    // 1) zero scratch
    {
        int n = NCELL / 2;          // float4 stores
        p2g_zero_kernel<<<(n + 255) / 256, 256>>>();
    }
    // 2) scatter
    {
        p2g_scatter_kernel<<<(L + 255) / 256, 256>>>(pos, prob, bidx, L);
    }
    // 3) finalize divide
    {
        p2g_finalize_kernel<<<(out_size + 255) / 256, 256>>>(out, out_size);
    }
}

// round 2
// speedup vs baseline: 1.3934x; 1.3934x over previous
#include <cuda_runtime.h>
#include <cstdint>

// ---------------------------------------------------------------------------
// P2G quadratic B-spline scatter, 64^3 grid, up to B=8 batches.
// out[b, cell] = sum_p w_p * prob_p / (sum_p w_p + 1e-7)
//
// Round-2 strategy:
//  - z-padded scratch layout: each (b,x,y) row holds 68 float2 cells
//    (slot = z + 2), so z-taps z in [-1, 64] land inside the row and
//    out-of-box taps hit pad slots that finalize never reads.
//  - the 3 contiguous z-taps (3 float2 = 24 B) always fit one 16B-aligned
//    4-cell window -> exactly 2x red.global.add.v4.f32 per (ox,oy) pair,
//    branchless. 18 REDG lanes/particle instead of 27.
// ---------------------------------------------------------------------------

#define GRID_N   64
#define GRID_N3  (GRID_N * GRID_N * GRID_N)
#define B_MAX    8
#define ROWLEN   68                         // 64 + 2 pad each side (16B-aligned stride: 544 B)
#define NROWS    (B_MAX * GRID_N * GRID_N)  // 32768
#define NCELL_SCRATCH (NROWS * ROWLEN)      // 2,228,224 float2 = 17.8 MB

__device__ float2 g_acc[NCELL_SCRATCH];     // (weight, weight*prob)

// ---------------------------------------------------------------------------

__global__ void p2g_zero_kernel(int n4) {
    // grid-stride zero of n4 float4 elements
    float4* p = reinterpret_cast<float4*>(g_acc);
    for (int i = blockIdx.x * blockDim.x + threadIdx.x; i < n4;
         i += gridDim.x * blockDim.x) {
        p[i] = make_float4(0.f, 0.f, 0.f, 0.f);
    }
}

// ---------------------------------------------------------------------------

__device__ __forceinline__ void red_add_v4(float2* addr,
                                           float a, float b, float c, float d) {
    asm volatile("red.global.add.v4.f32 [%0], {%1, %2, %3, %4};"
                 :: "l"(addr), "f"(a), "f"(b), "f"(c), "f"(d)
                 : "memory");
}

__global__ void __launch_bounds__(256)
p2g_scatter_kernel(const float* __restrict__ pos,
                   const float* __restrict__ prob,
                   const int*   __restrict__ bidx,
                   int L) {
    int i = blockIdx.x * blockDim.x + threadIdx.x;
    if (i >= L) return;

    const float EPS_CLIP = 1e-5f;
    const float HI       = 1.0f - 1e-5f;

    float px = pos[3 * i + 0];
    float py = pos[3 * i + 1];
    float pz = pos[3 * i + 2];
    px = fminf(fmaxf(px, EPS_CLIP), HI);
    py = fminf(fmaxf(py, EPS_CLIP), HI);
    pz = fminf(fmaxf(pz, EPS_CLIP), HI);

    float Xx = px * 64.0f;
    float Xy = py * 64.0f;
    float Xz = pz * 64.0f;

    int bx = (int)Xx;
    int by = (int)Xy;
    int bz = (int)Xz;

    float fx = Xx - (float)bx;
    float fy = Xy - (float)by;
    float fz = Xz - (float)bz;

    float wx[3], wy[3], wz0, wz1, wz2;
    wx[0] = 0.5f * (1.0f - fx) * (1.0f - fx);
    wx[1] = 0.75f - (fx - 0.5f) * (fx - 0.5f);
    wx[2] = 0.5f * fx * fx;
    wy[0] = 0.5f * (1.0f - fy) * (1.0f - fy);
    wy[1] = 0.75f - (fy - 0.5f) * (fy - 0.5f);
    wy[2] = 0.5f * fy * fy;
    wz0 = 0.5f * (1.0f - fz) * (1.0f - fz);
    wz1 = 0.75f - (fz - 0.5f) * (fz - 0.5f);
    wz2 = 0.5f * fz * fz;

    float p_val = prob[i];
    int   brow  = bidx[i] * (GRID_N * GRID_N);

    // z-slot of first tap (tz = bz-1 -> slot bz+1), shifted into an aligned
    // 4-cell window [a, a+4): window cells a..a+3 carry weights z0..z3.
    int zb    = bz + 1;          // in [1, 64]
    int shift = zb & 1;
    int a     = zb - shift;      // even, in [0, 64]; a+3 <= 67 < ROWLEN

    float z0 = shift ? 0.0f : wz0;
    float z1 = shift ? wz0  : wz1;
    float z2 = shift ? wz1  : wz2;
    float z3 = shift ? wz2  : 0.0f;
    float q0 = z0 * p_val;
    float q1 = z1 * p_val;
    float q2 = z2 * p_val;
    float q3 = z3 * p_val;

    #pragma unroll
    for (int ox = 0; ox < 3; ox++) {
        int tx = bx - 1 + ox;
        if ((unsigned)tx >= (unsigned)GRID_N) continue;
        int xrow = brow + tx * GRID_N;
        #pragma unroll
        for (int oy = 0; oy < 3; oy++) {
            int ty = by - 1 + oy;
            if ((unsigned)ty >= (unsigned)GRID_N) continue;
            float c = wx[ox] * wy[oy];
            float2* base = g_acc + (size_t)(xrow + ty) * ROWLEN + a;
            red_add_v4(base,     c * z0, c * q0, c * z1, c * q1);
            red_add_v4(base + 2, c * z2, c * q2, c * z3, c * q3);
        }
    }
}

// ---------------------------------------------------------------------------

__global__ void p2g_finalize_kernel(float* __restrict__ out, int n) {
    int i = blockIdx.x * blockDim.x + threadIdx.x;
    if (i < n) {
        int b   = i >> 18;              // / 262144
        int rem = i & (GRID_N3 - 1);
        int row = (b << 12) + (rem >> 6);       // b*4096 + x*64 + y
        int z   = rem & 63;
        float2 acc = g_acc[(size_t)row * ROWLEN + z + 2];
        out[i] = acc.y / (acc.x + 1e-7f);
    }
}

// ---------------------------------------------------------------------------

extern "C" void kernel_launch(void* const* d_in, const int* in_sizes, int n_in,
                              void* d_out, int out_size) {
    const float* pos  = (const float*)d_in[0];
    const float* prob = (const float*)d_in[1];
    const int*   bidx = (const int*)d_in[2];
    float*       out  = (float*)d_out;

    int L = in_sizes[1];                        // particle count (prob size)

    // rows actually used = B * 64 * 64 ; zero exactly those (as float4)
    int B      = out_size / GRID_N3;
    int rows   = B * GRID_N * GRID_N;
    int ncell  = rows * ROWLEN;                 // float2 cells
    int n4     = ncell / 2;                     // float4 elements

    p2g_zero_kernel<<<1184, 512>>>(n4);         // 148 SMs * 8 blocks
    p2g_scatter_kernel<<<(L + 255) / 256, 256>>>(pos, prob, bidx, L);
    p2g_finalize_kernel<<<(out_size + 255) / 256, 256>>>(out, out_size);
}